// round 1
// baseline (speedup 1.0000x reference)
#include <cuda_runtime.h>

// Problem constants
#define BATCH  2
#define T_SEQ  2048
#define WID    1024
#define HEADS  16
#define CH     64
#define W3     3072   // 3 * WID
#define MROWS  (BATCH * T_SEQ)   // 4096

// Scratch (allocation-free rule: use __device__ globals)
__device__ float g_qkv [BATCH * T_SEQ * W3];    // 48 MB
__device__ float g_attn[BATCH * T_SEQ * WID];   // 16 MB
__device__ float g_kmean[BATCH * HEADS * CH];
__device__ float g_pos [BATCH * T_SEQ];
__device__ float g_aw  [BATCH * T_SEQ];

// ---------------------------------------------------------------------------
// SGEMM: C[M,N] = A[M,K] @ B[K,N] + bias[N].  M,N multiples of 128, K of 8.
// 128x128 block tile, 8x8 per thread, 256 threads.
// ---------------------------------------------------------------------------
__global__ __launch_bounds__(256) void sgemm_bias(
    const float* __restrict__ A, const float* __restrict__ B,
    const float* __restrict__ bias, float* __restrict__ C,
    int M, int N, int K)
{
    __shared__ float As[8][128];
    __shared__ float Bs[8][128];

    const int tid  = threadIdx.x;
    const int row0 = blockIdx.y * 128;
    const int col0 = blockIdx.x * 128;
    const int tx   = tid & 15;      // 0..15 -> 8 cols each
    const int ty   = tid >> 4;      // 0..15 -> 8 rows each

    const int a_row = tid >> 1;           // 0..127
    const int a_col = (tid & 1) * 4;      // 0 or 4
    const int b_row = tid >> 5;           // 0..7
    const int b_col = (tid & 31) * 4;     // 0..124

    const float* Aptr = A + (size_t)(row0 + a_row) * K + a_col;
    const float* Bptr = B + (size_t)b_row * N + col0 + b_col;

    float acc[8][8];
    #pragma unroll
    for (int i = 0; i < 8; i++)
        #pragma unroll
        for (int j = 0; j < 8; j++) acc[i][j] = 0.f;

    for (int k0 = 0; k0 < K; k0 += 8) {
        float4 av = *(const float4*)(Aptr + k0);
        float4 bv = *(const float4*)(Bptr + (size_t)k0 * N);
        As[a_col + 0][a_row] = av.x;
        As[a_col + 1][a_row] = av.y;
        As[a_col + 2][a_row] = av.z;
        As[a_col + 3][a_row] = av.w;
        *(float4*)&Bs[b_row][b_col] = bv;
        __syncthreads();

        #pragma unroll
        for (int k = 0; k < 8; k++) {
            float ar[8], br[8];
            *(float4*)&ar[0] = *(const float4*)&As[k][ty * 8];
            *(float4*)&ar[4] = *(const float4*)&As[k][ty * 8 + 4];
            *(float4*)&br[0] = *(const float4*)&Bs[k][tx * 8];
            *(float4*)&br[4] = *(const float4*)&Bs[k][tx * 8 + 4];
            #pragma unroll
            for (int i = 0; i < 8; i++)
                #pragma unroll
                for (int j = 0; j < 8; j++)
                    acc[i][j] = fmaf(ar[i], br[j], acc[i][j]);
        }
        __syncthreads();
    }

    const int col = col0 + tx * 8;
    float4 b0 = *(const float4*)&bias[col];
    float4 b1 = *(const float4*)&bias[col + 4];
    #pragma unroll
    for (int i = 0; i < 8; i++) {
        const int row = row0 + ty * 8 + i;
        float4 o0 = make_float4(acc[i][0] + b0.x, acc[i][1] + b0.y,
                                acc[i][2] + b0.z, acc[i][3] + b0.w);
        float4 o1 = make_float4(acc[i][4] + b1.x, acc[i][5] + b1.y,
                                acc[i][6] + b1.z, acc[i][7] + b1.w);
        *(float4*)&C[(size_t)row * N + col]     = o0;
        *(float4*)&C[(size_t)row * N + col + 4] = o1;
    }
}

// ---------------------------------------------------------------------------
// k_mean[b,h,c] = mean over t of k[b,t,h,c]. One block per (b,h).
// ---------------------------------------------------------------------------
__global__ __launch_bounds__(256) void kmean_kernel()
{
    const int bh = blockIdx.x;
    const int b = bh >> 4, h = bh & 15;
    const int c  = threadIdx.x & 63;
    const int tg = threadIdx.x >> 6;   // 0..3
    const float* base = g_qkv + (size_t)b * T_SEQ * W3 + h * 192 + CH + c;
    float s = 0.f;
    for (int t = tg; t < T_SEQ; t += 4) s += base[(size_t)t * W3];
    __shared__ float red[4][64];
    red[tg][c] = s;
    __syncthreads();
    if (tg == 0) {
        float tot = red[0][c] + red[1][c] + red[2][c] + red[3][c];
        g_kmean[bh * CH + c] = tot * (1.f / (float)T_SEQ);
    }
}

// ---------------------------------------------------------------------------
// pos[b,t] = (1/8) * sum_{h,c} q[b,t,h,c] * k_mean[b,h,c].  One block per (b,t).
// ---------------------------------------------------------------------------
__global__ __launch_bounds__(256) void pos_kernel()
{
    const int bt = blockIdx.x;
    const int b  = bt >> 11;
    const float* qb = g_qkv + (size_t)bt * W3;
    const float* km = g_kmean + b * WID;
    float s = 0.f;
    for (int j = threadIdx.x; j < WID; j += 256) {
        const int h = j >> 6, c = j & 63;
        s += qb[h * 192 + c] * km[j];
    }
    #pragma unroll
    for (int msk = 16; msk; msk >>= 1) s += __shfl_xor_sync(0xffffffffu, s, msk);
    __shared__ float red[8];
    if ((threadIdx.x & 31) == 0) red[threadIdx.x >> 5] = s;
    __syncthreads();
    if (threadIdx.x == 0) {
        float t = 0.f;
        #pragma unroll
        for (int w = 0; w < 8; w++) t += red[w];
        g_pos[bt] = t * 0.125f;
    }
}

// ---------------------------------------------------------------------------
// aw[b,t] = (pos - min) / (max - min + 1e-6).  One block per batch.
// ---------------------------------------------------------------------------
__global__ __launch_bounds__(256) void aw_kernel()
{
    const int b = blockIdx.x;
    const int tid = threadIdx.x;
    float vals[8];
    float mn = 1e30f, mx = -1e30f;
    #pragma unroll
    for (int k = 0; k < 8; k++) {
        float v = g_pos[b * T_SEQ + tid + 256 * k];
        vals[k] = v;
        mn = fminf(mn, v);
        mx = fmaxf(mx, v);
    }
    __shared__ float smn[256], smx[256];
    smn[tid] = mn; smx[tid] = mx;
    __syncthreads();
    for (int s = 128; s; s >>= 1) {
        if (tid < s) {
            smn[tid] = fminf(smn[tid], smn[tid + s]);
            smx[tid] = fmaxf(smx[tid], smx[tid + s]);
        }
        __syncthreads();
    }
    const float gmn = smn[0];
    const float inv = 1.f / (smx[0] - smn[0] + 1e-6f);
    #pragma unroll
    for (int k = 0; k < 8; k++)
        g_aw[b * T_SEQ + tid + 256 * k] = (vals[k] - gmn) * inv;
}

// ---------------------------------------------------------------------------
// Flash attention, fp32, 64-query tile per block, online softmax.
// grid = (T/64, B*H), 256 threads, 16x16 thread grid, 4x4 regs each.
// smem: Qt (Q^T, pre-scaled by 1/8), KP (K^T then P), Vs. 48 KB total.
// Applies adaptive weight aw[b,t] at the write.
// ---------------------------------------------------------------------------
__global__ __launch_bounds__(256) void flash_attn()
{
    __shared__ float Qt[64 * 64];
    __shared__ float KP[64 * 64];
    __shared__ float Vs[64 * 64];

    const int tid = threadIdx.x;
    const int bh  = blockIdx.y;
    const int b = bh >> 4, h = bh & 15;
    const int q0 = blockIdx.x * 64;
    const float* base = g_qkv + (size_t)b * T_SEQ * W3 + h * 192;

    // Load Q tile transposed (Qt[c][r]), pre-scaled by scale^2 = 1/8.
    #pragma unroll
    for (int ii = 0; ii < 4; ii++) {
        const int id = tid + 256 * ii;
        const int row = id >> 4, c4 = (id & 15) * 4;
        float4 v = *(const float4*)(base + (size_t)(q0 + row) * W3 + c4);
        Qt[(c4 + 0) * 64 + row] = v.x * 0.125f;
        Qt[(c4 + 1) * 64 + row] = v.y * 0.125f;
        Qt[(c4 + 2) * 64 + row] = v.z * 0.125f;
        Qt[(c4 + 3) * 64 + row] = v.w * 0.125f;
    }

    const int tx = tid & 15, ty = tid >> 4;
    float m[4], l[4], O[4][4];
    #pragma unroll
    for (int i = 0; i < 4; i++) {
        m[i] = -1e30f; l[i] = 0.f;
        #pragma unroll
        for (int j = 0; j < 4; j++) O[i][j] = 0.f;
    }

    for (int t0 = 0; t0 < T_SEQ; t0 += 64) {
        __syncthreads();   // protect KP/Vs reuse from previous iteration
        // Load K tile transposed (KP[c][r]) and V tile direct (Vs[r][c]).
        #pragma unroll
        for (int ii = 0; ii < 4; ii++) {
            const int id = tid + 256 * ii;
            const int row = id >> 4, c4 = (id & 15) * 4;
            const float* krow = base + (size_t)(t0 + row) * W3;
            float4 kv = *(const float4*)(krow + CH + c4);
            KP[(c4 + 0) * 64 + row] = kv.x;
            KP[(c4 + 1) * 64 + row] = kv.y;
            KP[(c4 + 2) * 64 + row] = kv.z;
            KP[(c4 + 3) * 64 + row] = kv.w;
            float4 vv = *(const float4*)(krow + 2 * CH + c4);
            *(float4*)&Vs[row * 64 + c4] = vv;
        }
        __syncthreads();

        // S = (Q/8) . K^T  (64x64, 4x4 per thread)
        float s[4][4];
        #pragma unroll
        for (int i = 0; i < 4; i++)
            #pragma unroll
            for (int j = 0; j < 4; j++) s[i][j] = 0.f;
        #pragma unroll 8
        for (int k = 0; k < 64; k++) {
            float4 qa = *(const float4*)&Qt[k * 64 + ty * 4];
            float4 kb = *(const float4*)&KP[k * 64 + tx * 4];
            s[0][0] = fmaf(qa.x, kb.x, s[0][0]); s[0][1] = fmaf(qa.x, kb.y, s[0][1]);
            s[0][2] = fmaf(qa.x, kb.z, s[0][2]); s[0][3] = fmaf(qa.x, kb.w, s[0][3]);
            s[1][0] = fmaf(qa.y, kb.x, s[1][0]); s[1][1] = fmaf(qa.y, kb.y, s[1][1]);
            s[1][2] = fmaf(qa.y, kb.z, s[1][2]); s[1][3] = fmaf(qa.y, kb.w, s[1][3]);
            s[2][0] = fmaf(qa.z, kb.x, s[2][0]); s[2][1] = fmaf(qa.z, kb.y, s[2][1]);
            s[2][2] = fmaf(qa.z, kb.z, s[2][2]); s[2][3] = fmaf(qa.z, kb.w, s[2][3]);
            s[3][0] = fmaf(qa.w, kb.x, s[3][0]); s[3][1] = fmaf(qa.w, kb.y, s[3][1]);
            s[3][2] = fmaf(qa.w, kb.z, s[3][2]); s[3][3] = fmaf(qa.w, kb.w, s[3][3]);
        }

        // Online softmax update. Row stats reduced across the 16-lane group
        // sharing ty (xor masks 1,2,4,8 stay inside the half-warp).
        #pragma unroll
        for (int i = 0; i < 4; i++) {
            float mx_ = fmaxf(fmaxf(s[i][0], s[i][1]), fmaxf(s[i][2], s[i][3]));
            #pragma unroll
            for (int msk = 1; msk < 16; msk <<= 1)
                mx_ = fmaxf(mx_, __shfl_xor_sync(0xffffffffu, mx_, msk));
            const float mnew = fmaxf(m[i], mx_);
            const float alpha = __expf(m[i] - mnew);
            m[i] = mnew;
            float sum_ = 0.f;
            #pragma unroll
            for (int j = 0; j < 4; j++) {
                s[i][j] = __expf(s[i][j] - mnew);
                sum_ += s[i][j];
            }
            #pragma unroll
            for (int msk = 1; msk < 16; msk <<= 1)
                sum_ += __shfl_xor_sync(0xffffffffu, sum_, msk);
            l[i] = l[i] * alpha + sum_;
            #pragma unroll
            for (int j = 0; j < 4; j++) O[i][j] *= alpha;
        }

        __syncthreads();   // everyone done reading KP as K^T
        // Write P (row-major Ps[r][s]) into KP.
        #pragma unroll
        for (int i = 0; i < 4; i++) {
            float4 pv = make_float4(s[i][0], s[i][1], s[i][2], s[i][3]);
            *(float4*)&KP[(ty * 4 + i) * 64 + tx * 4] = pv;
        }
        __syncthreads();

        // O += P @ V
        #pragma unroll 8
        for (int ss = 0; ss < 64; ss++) {
            float4 vv = *(const float4*)&Vs[ss * 64 + tx * 4];
            const float p0 = KP[(ty * 4 + 0) * 64 + ss];
            const float p1 = KP[(ty * 4 + 1) * 64 + ss];
            const float p2 = KP[(ty * 4 + 2) * 64 + ss];
            const float p3 = KP[(ty * 4 + 3) * 64 + ss];
            O[0][0] = fmaf(p0, vv.x, O[0][0]); O[0][1] = fmaf(p0, vv.y, O[0][1]);
            O[0][2] = fmaf(p0, vv.z, O[0][2]); O[0][3] = fmaf(p0, vv.w, O[0][3]);
            O[1][0] = fmaf(p1, vv.x, O[1][0]); O[1][1] = fmaf(p1, vv.y, O[1][1]);
            O[1][2] = fmaf(p1, vv.z, O[1][2]); O[1][3] = fmaf(p1, vv.w, O[1][3]);
            O[2][0] = fmaf(p2, vv.x, O[2][0]); O[2][1] = fmaf(p2, vv.y, O[2][1]);
            O[2][2] = fmaf(p2, vv.z, O[2][2]); O[2][3] = fmaf(p2, vv.w, O[2][3]);
            O[3][0] = fmaf(p3, vv.x, O[3][0]); O[3][1] = fmaf(p3, vv.y, O[3][1]);
            O[3][2] = fmaf(p3, vv.z, O[3][2]); O[3][3] = fmaf(p3, vv.w, O[3][3]);
        }
    }

    // Epilogue: normalize by l, apply adaptive weight, write [b,t,h*64+c].
    #pragma unroll
    for (int i = 0; i < 4; i++) {
        const int t = q0 + ty * 4 + i;
        const float w = g_aw[b * T_SEQ + t] / l[i];
        float4 o = make_float4(O[i][0] * w, O[i][1] * w, O[i][2] * w, O[i][3] * w);
        *(float4*)&g_attn[((size_t)(b * T_SEQ + t)) * WID + h * CH + tx * 4] = o;
    }
}

// ---------------------------------------------------------------------------
extern "C" void kernel_launch(void* const* d_in, const int* in_sizes, int n_in,
                              void* d_out, int out_size)
{
    const float* x     = (const float*)d_in[0];
    const float* Wqkv  = (const float*)d_in[1];
    const float* bqkv  = (const float*)d_in[2];
    const float* Wproj = (const float*)d_in[3];
    const float* bproj = (const float*)d_in[4];
    float* out = (float*)d_out;

    float *qkv, *attn;
    cudaGetSymbolAddress((void**)&qkv,  g_qkv);
    cudaGetSymbolAddress((void**)&attn, g_attn);

    // 1) qkv = x @ W_qkv + b_qkv       [4096,1024]x[1024,3072]
    sgemm_bias<<<dim3(W3 / 128, MROWS / 128), 256>>>(x, Wqkv, bqkv, qkv, MROWS, W3, WID);
    // 2) k_mean
    kmean_kernel<<<BATCH * HEADS, 256>>>();
    // 3) pos = (q . k_mean)/8
    pos_kernel<<<BATCH * T_SEQ, 256>>>();
    // 4) adaptive weight
    aw_kernel<<<BATCH, 256>>>();
    // 5) attention (applies aw)
    flash_attn<<<dim3(T_SEQ / 64, BATCH * HEADS), 256>>>();
    // 6) out = attn @ W_proj + b_proj  [4096,1024]x[1024,1024]
    sgemm_bias<<<dim3(WID / 128, MROWS / 128), 256>>>(attn, Wproj, bproj, out, MROWS, WID, WID);
}

// round 4
// speedup vs baseline: 1.0211x; 1.0211x over previous
#include <cuda_runtime.h>
#include <cstdint>

// Problem constants
#define BATCH  2
#define T_SEQ  2048
#define WID    1024
#define HEADS  16
#define CH     64
#define W3     3072
#define MROWS  (BATCH * T_SEQ)   // 4096

// Scratch (allocation-free rule: use __device__ globals)
__device__ float g_qkv [BATCH * T_SEQ * W3];    // 48 MB
__device__ float g_attn[BATCH * T_SEQ * WID];   // 16 MB
__device__ float g_kmean[BATCH * HEADS * CH];
__device__ float g_pos [BATCH * T_SEQ];
__device__ float g_aw  [BATCH * T_SEQ];

// ---------------------------------------------------------------------------
// mma.sync m16n8k8 tf32 helpers (plain PTX — legal in compute_103 PTX)
// ---------------------------------------------------------------------------
__device__ __forceinline__ void mma_tf32(float* c, const float* a, const float* b)
{
    asm volatile(
        "mma.sync.aligned.m16n8k8.row.col.f32.tf32.tf32.f32 "
        "{%0,%1,%2,%3}, {%4,%5,%6,%7}, {%8,%9}, {%0,%1,%2,%3};"
        : "+f"(c[0]), "+f"(c[1]), "+f"(c[2]), "+f"(c[3])
        : "r"(__float_as_uint(a[0])), "r"(__float_as_uint(a[1])),
          "r"(__float_as_uint(a[2])), "r"(__float_as_uint(a[3])),
          "r"(__float_as_uint(b[0])), "r"(__float_as_uint(b[1])));
}

// fp32 -> tf32 round-to-nearest (value kept in fp32 container)
__device__ __forceinline__ float f2tf32(float x) {
    uint32_t u;
    asm("cvt.rna.tf32.f32 %0, %1;" : "=r"(u) : "f"(x));
    return __uint_as_float(u);
}

// Fragment loaders. lane decomposed as gid = lane>>2 (0..7), tig = lane&3.
// A (m16 x k8), row-major in smem with row stride SA:
//   a0=[r+gid][k+tig] a1=[r+gid+8][k+tig] a2=[r+gid][k+tig+4] a3=[r+gid+8][k+tig+4]
__device__ __forceinline__ void frag_a(float* a, const float* S, int SA,
                                       int r, int k, int gid, int tig)
{
    const float* p0 = S + (r + gid) * SA + k + tig;
    const float* p1 = S + (r + gid + 8) * SA + k + tig;
    a[0] = p0[0]; a[1] = p1[0]; a[2] = p0[4]; a[3] = p1[4];
}
// B (k8 x n8), stored [k][n] with row stride SB:
//   b0=[k+tig][n+gid]  b1=[k+tig+4][n+gid]
__device__ __forceinline__ void frag_b(float* b, const float* S, int SB,
                                       int k, int n, int gid, int tig)
{
    b[0] = S[(k + tig) * SB + n + gid];
    b[1] = S[(k + tig + 4) * SB + n + gid];
}

// ---------------------------------------------------------------------------
// Tensor-core GEMM (3xTF32 via mma.sync): C[M,N] = A[M,K] @ B[K,N] + bias[N]
// CTA tile 128x128, K-chunk 32, 256 threads = 8 warps (4 M x 2 N),
// warp tile 32x64. Smem strides padded for conflict-free fragment loads.
// ---------------------------------------------------------------------------
static constexpr int GA_S = 36;    // A smem row stride (floats)
static constexpr int GB_S = 136;   // B smem row stride (floats)
static constexpr int G_AH = 0;
static constexpr int G_AL = 128 * GA_S;              // 4608
static constexpr int G_BH = 2 * 128 * GA_S;          // 9216
static constexpr int G_BL = G_BH + 32 * GB_S;        // 13568
static constexpr int G_TOT = (G_BL + 32 * GB_S) * 4; // 71680 bytes

__global__ __launch_bounds__(256) void gemm_tc(
    const float* __restrict__ A, const float* __restrict__ B,
    const float* __restrict__ bias, float* __restrict__ C,
    int N, int K)
{
    extern __shared__ float sm[];
    float* Ah = sm + G_AH;
    float* Al = sm + G_AL;
    float* Bh = sm + G_BH;
    float* Bl = sm + G_BL;

    const int tid = threadIdx.x;
    const int wid = tid >> 5;
    const int lane = tid & 31;
    const int gid = lane >> 2, tig = lane & 3;
    const int wm = (wid >> 1) * 32;   // warp row offset in tile
    const int wn = (wid & 1) * 64;    // warp col offset in tile
    const int row0 = blockIdx.y * 128;
    const int col0 = blockIdx.x * 128;

    // stagers
    const int ar = tid >> 1;            // 0..127
    const int ak = (tid & 1) * 16;      // 0 or 16
    const int bk = tid >> 3;            // 0..31
    const int bn = (tid & 7) * 16;      // 0..112

    const float* Ap = A + (size_t)(row0 + ar) * K + ak;
    const float* Bp0 = B + col0 + bn;

    float c[2][8][4];
    #pragma unroll
    for (int i = 0; i < 2; i++)
        #pragma unroll
        for (int j = 0; j < 8; j++)
            #pragma unroll
            for (int q = 0; q < 4; q++) c[i][j][q] = 0.f;

    for (int kc = 0; kc < K; kc += 32) {
        __syncthreads();
        // stage A (128x32) hi/lo
        #pragma unroll
        for (int i = 0; i < 4; i++) {
            float4 v = *(const float4*)(Ap + kc + i * 4);
            float4 h, l;
            h.x = f2tf32(v.x); l.x = f2tf32(v.x - h.x);
            h.y = f2tf32(v.y); l.y = f2tf32(v.y - h.y);
            h.z = f2tf32(v.z); l.z = f2tf32(v.z - h.z);
            h.w = f2tf32(v.w); l.w = f2tf32(v.w - h.w);
            *(float4*)(Ah + ar * GA_S + ak + i * 4) = h;
            *(float4*)(Al + ar * GA_S + ak + i * 4) = l;
        }
        // stage B (32x128) hi/lo
        {
            const float* Bp = Bp0 + (size_t)(kc + bk) * N;
            #pragma unroll
            for (int i = 0; i < 4; i++) {
                float4 v = *(const float4*)(Bp + i * 4);
                float4 h, l;
                h.x = f2tf32(v.x); l.x = f2tf32(v.x - h.x);
                h.y = f2tf32(v.y); l.y = f2tf32(v.y - h.y);
                h.z = f2tf32(v.z); l.z = f2tf32(v.z - h.z);
                h.w = f2tf32(v.w); l.w = f2tf32(v.w - h.w);
                *(float4*)(Bh + bk * GB_S + bn + i * 4) = h;
                *(float4*)(Bl + bk * GB_S + bn + i * 4) = l;
            }
        }
        __syncthreads();

        #pragma unroll
        for (int ks = 0; ks < 4; ks++) {
            float ah[2][4], al[2][4];
            frag_a(ah[0], Ah, GA_S, wm,      ks * 8, gid, tig);
            frag_a(ah[1], Ah, GA_S, wm + 16, ks * 8, gid, tig);
            frag_a(al[0], Al, GA_S, wm,      ks * 8, gid, tig);
            frag_a(al[1], Al, GA_S, wm + 16, ks * 8, gid, tig);
            #pragma unroll
            for (int j = 0; j < 8; j++) {
                float bh[2], bl[2];
                frag_b(bh, Bh, GB_S, ks * 8, wn + j * 8, gid, tig);
                frag_b(bl, Bl, GB_S, ks * 8, wn + j * 8, gid, tig);
                #pragma unroll
                for (int i = 0; i < 2; i++) {
                    mma_tf32(c[i][j], ah[i], bh);
                    mma_tf32(c[i][j], ah[i], bl);
                    mma_tf32(c[i][j], al[i], bh);
                }
            }
        }
    }

    // epilogue: c frags + bias -> gmem (float2 per fragment half-row)
    #pragma unroll
    for (int i = 0; i < 2; i++) {
        const int r0 = row0 + wm + i * 16 + gid;
        #pragma unroll
        for (int j = 0; j < 8; j++) {
            const int col = col0 + wn + j * 8 + 2 * tig;
            float2 bv = *(const float2*)&bias[col];
            float2 o0 = make_float2(c[i][j][0] + bv.x, c[i][j][1] + bv.y);
            float2 o1 = make_float2(c[i][j][2] + bv.x, c[i][j][3] + bv.y);
            *(float2*)&C[(size_t)r0 * N + col]       = o0;
            *(float2*)&C[(size_t)(r0 + 8) * N + col] = o1;
        }
    }
}

// ---------------------------------------------------------------------------
// k_mean[b,h,c] = mean over t of k[b,t,h,c]. One block per (b,h).
// ---------------------------------------------------------------------------
__global__ __launch_bounds__(256) void kmean_kernel()
{
    const int bh = blockIdx.x;
    const int b = bh >> 4, h = bh & 15;
    const int c  = threadIdx.x & 63;
    const int tg = threadIdx.x >> 6;   // 0..3
    const float* base = g_qkv + (size_t)b * T_SEQ * W3 + h * 192 + CH + c;
    float s = 0.f;
    for (int t = tg; t < T_SEQ; t += 4) s += base[(size_t)t * W3];
    __shared__ float red[4][64];
    red[tg][c] = s;
    __syncthreads();
    if (tg == 0) {
        float tot = red[0][c] + red[1][c] + red[2][c] + red[3][c];
        g_kmean[bh * CH + c] = tot * (1.f / (float)T_SEQ);
    }
}

// ---------------------------------------------------------------------------
// pos[b,t] = (1/8) * sum_{h,c} q[b,t,h,c] * k_mean[b,h,c].  One block per (b,t).
// ---------------------------------------------------------------------------
__global__ __launch_bounds__(256) void pos_kernel()
{
    const int bt = blockIdx.x;
    const int b  = bt >> 11;
    const float* qb = g_qkv + (size_t)bt * W3;
    const float* km = g_kmean + b * WID;
    float s = 0.f;
    for (int j = threadIdx.x; j < WID; j += 256) {
        const int h = j >> 6, c = j & 63;
        s += qb[h * 192 + c] * km[j];
    }
    #pragma unroll
    for (int msk = 16; msk; msk >>= 1) s += __shfl_xor_sync(0xffffffffu, s, msk);
    __shared__ float red[8];
    if ((threadIdx.x & 31) == 0) red[threadIdx.x >> 5] = s;
    __syncthreads();
    if (threadIdx.x == 0) {
        float t = 0.f;
        #pragma unroll
        for (int w = 0; w < 8; w++) t += red[w];
        g_pos[bt] = t * 0.125f;
    }
}

// ---------------------------------------------------------------------------
// aw[b,t] = (pos - min) / (max - min + 1e-6).  One block per batch.
// ---------------------------------------------------------------------------
__global__ __launch_bounds__(256) void aw_kernel()
{
    const int b = blockIdx.x;
    const int tid = threadIdx.x;
    float vals[8];
    float mn = 1e30f, mx = -1e30f;
    #pragma unroll
    for (int k = 0; k < 8; k++) {
        float v = g_pos[b * T_SEQ + tid + 256 * k];
        vals[k] = v;
        mn = fminf(mn, v);
        mx = fmaxf(mx, v);
    }
    __shared__ float smn[256], smx[256];
    smn[tid] = mn; smx[tid] = mx;
    __syncthreads();
    for (int s = 128; s; s >>= 1) {
        if (tid < s) {
            smn[tid] = fminf(smn[tid], smn[tid + s]);
            smx[tid] = fmaxf(smx[tid], smx[tid + s]);
        }
        __syncthreads();
    }
    const float gmn = smn[0];
    const float inv = 1.f / (smx[0] - smn[0] + 1e-6f);
    #pragma unroll
    for (int k = 0; k < 8; k++)
        g_aw[b * T_SEQ + tid + 256 * k] = (vals[k] - gmn) * inv;
}

// ---------------------------------------------------------------------------
// Flash attention, fp32 SIMT (R1-proven), 64-query tile, online softmax.
// grid = (T/64, B*H), 256 threads, 16x16 thread grid, 4x4 regs each.
// ---------------------------------------------------------------------------
__global__ __launch_bounds__(256) void flash_attn()
{
    __shared__ float Qt[64 * 64];
    __shared__ float KP[64 * 64];
    __shared__ float Vs[64 * 64];

    const int tid = threadIdx.x;
    const int bh  = blockIdx.y;
    const int b = bh >> 4, h = bh & 15;
    const int q0 = blockIdx.x * 64;
    const float* base = g_qkv + (size_t)b * T_SEQ * W3 + h * 192;

    #pragma unroll
    for (int ii = 0; ii < 4; ii++) {
        const int id = tid + 256 * ii;
        const int row = id >> 4, c4 = (id & 15) * 4;
        float4 v = *(const float4*)(base + (size_t)(q0 + row) * W3 + c4);
        Qt[(c4 + 0) * 64 + row] = v.x * 0.125f;
        Qt[(c4 + 1) * 64 + row] = v.y * 0.125f;
        Qt[(c4 + 2) * 64 + row] = v.z * 0.125f;
        Qt[(c4 + 3) * 64 + row] = v.w * 0.125f;
    }

    const int tx = tid & 15, ty = tid >> 4;
    float m[4], l[4], O[4][4];
    #pragma unroll
    for (int i = 0; i < 4; i++) {
        m[i] = -1e30f; l[i] = 0.f;
        #pragma unroll
        for (int j = 0; j < 4; j++) O[i][j] = 0.f;
    }

    for (int t0 = 0; t0 < T_SEQ; t0 += 64) {
        __syncthreads();
        #pragma unroll
        for (int ii = 0; ii < 4; ii++) {
            const int id = tid + 256 * ii;
            const int row = id >> 4, c4 = (id & 15) * 4;
            const float* krow = base + (size_t)(t0 + row) * W3;
            float4 kv = *(const float4*)(krow + CH + c4);
            KP[(c4 + 0) * 64 + row] = kv.x;
            KP[(c4 + 1) * 64 + row] = kv.y;
            KP[(c4 + 2) * 64 + row] = kv.z;
            KP[(c4 + 3) * 64 + row] = kv.w;
            float4 vv = *(const float4*)(krow + 2 * CH + c4);
            *(float4*)&Vs[row * 64 + c4] = vv;
        }
        __syncthreads();

        float s[4][4];
        #pragma unroll
        for (int i = 0; i < 4; i++)
            #pragma unroll
            for (int j = 0; j < 4; j++) s[i][j] = 0.f;
        #pragma unroll 8
        for (int k = 0; k < 64; k++) {
            float4 qa = *(const float4*)&Qt[k * 64 + ty * 4];
            float4 kb = *(const float4*)&KP[k * 64 + tx * 4];
            s[0][0] = fmaf(qa.x, kb.x, s[0][0]); s[0][1] = fmaf(qa.x, kb.y, s[0][1]);
            s[0][2] = fmaf(qa.x, kb.z, s[0][2]); s[0][3] = fmaf(qa.x, kb.w, s[0][3]);
            s[1][0] = fmaf(qa.y, kb.x, s[1][0]); s[1][1] = fmaf(qa.y, kb.y, s[1][1]);
            s[1][2] = fmaf(qa.y, kb.z, s[1][2]); s[1][3] = fmaf(qa.y, kb.w, s[1][3]);
            s[2][0] = fmaf(qa.z, kb.x, s[2][0]); s[2][1] = fmaf(qa.z, kb.y, s[2][1]);
            s[2][2] = fmaf(qa.z, kb.z, s[2][2]); s[2][3] = fmaf(qa.z, kb.w, s[2][3]);
            s[3][0] = fmaf(qa.w, kb.x, s[3][0]); s[3][1] = fmaf(qa.w, kb.y, s[3][1]);
            s[3][2] = fmaf(qa.w, kb.z, s[3][2]); s[3][3] = fmaf(qa.w, kb.w, s[3][3]);
        }

        #pragma unroll
        for (int i = 0; i < 4; i++) {
            float mx_ = fmaxf(fmaxf(s[i][0], s[i][1]), fmaxf(s[i][2], s[i][3]));
            #pragma unroll
            for (int msk = 1; msk < 16; msk <<= 1)
                mx_ = fmaxf(mx_, __shfl_xor_sync(0xffffffffu, mx_, msk));
            const float mnew = fmaxf(m[i], mx_);
            const float alpha = __expf(m[i] - mnew);
            m[i] = mnew;
            float sum_ = 0.f;
            #pragma unroll
            for (int j = 0; j < 4; j++) {
                s[i][j] = __expf(s[i][j] - mnew);
                sum_ += s[i][j];
            }
            #pragma unroll
            for (int msk = 1; msk < 16; msk <<= 1)
                sum_ += __shfl_xor_sync(0xffffffffu, sum_, msk);
            l[i] = l[i] * alpha + sum_;
            #pragma unroll
            for (int j = 0; j < 4; j++) O[i][j] *= alpha;
        }

        __syncthreads();
        #pragma unroll
        for (int i = 0; i < 4; i++) {
            float4 pv = make_float4(s[i][0], s[i][1], s[i][2], s[i][3]);
            *(float4*)&KP[(ty * 4 + i) * 64 + tx * 4] = pv;
        }
        __syncthreads();

        #pragma unroll 8
        for (int ss = 0; ss < 64; ss++) {
            float4 vv = *(const float4*)&Vs[ss * 64 + tx * 4];
            const float p0 = KP[(ty * 4 + 0) * 64 + ss];
            const float p1 = KP[(ty * 4 + 1) * 64 + ss];
            const float p2 = KP[(ty * 4 + 2) * 64 + ss];
            const float p3 = KP[(ty * 4 + 3) * 64 + ss];
            O[0][0] = fmaf(p0, vv.x, O[0][0]); O[0][1] = fmaf(p0, vv.y, O[0][1]);
            O[0][2] = fmaf(p0, vv.z, O[0][2]); O[0][3] = fmaf(p0, vv.w, O[0][3]);
            O[1][0] = fmaf(p1, vv.x, O[1][0]); O[1][1] = fmaf(p1, vv.y, O[1][1]);
            O[1][2] = fmaf(p1, vv.z, O[1][2]); O[1][3] = fmaf(p1, vv.w, O[1][3]);
            O[2][0] = fmaf(p2, vv.x, O[2][0]); O[2][1] = fmaf(p2, vv.y, O[2][1]);
            O[2][2] = fmaf(p2, vv.z, O[2][2]); O[2][3] = fmaf(p2, vv.w, O[2][3]);
            O[3][0] = fmaf(p3, vv.x, O[3][0]); O[3][1] = fmaf(p3, vv.y, O[3][1]);
            O[3][2] = fmaf(p3, vv.z, O[3][2]); O[3][3] = fmaf(p3, vv.w, O[3][3]);
        }
    }

    #pragma unroll
    for (int i = 0; i < 4; i++) {
        const int t = q0 + ty * 4 + i;
        const float w = g_aw[b * T_SEQ + t] / l[i];
        float4 o = make_float4(O[i][0] * w, O[i][1] * w, O[i][2] * w, O[i][3] * w);
        *(float4*)&g_attn[((size_t)(b * T_SEQ + t)) * WID + h * CH + tx * 4] = o;
    }
}

// ---------------------------------------------------------------------------
extern "C" void kernel_launch(void* const* d_in, const int* in_sizes, int n_in,
                              void* d_out, int out_size)
{
    const float* x     = (const float*)d_in[0];
    const float* Wqkv  = (const float*)d_in[1];
    const float* bqkv  = (const float*)d_in[2];
    const float* Wproj = (const float*)d_in[3];
    const float* bproj = (const float*)d_in[4];
    float* out = (float*)d_out;

    float *qkv, *attn;
    cudaGetSymbolAddress((void**)&qkv,  g_qkv);
    cudaGetSymbolAddress((void**)&attn, g_attn);

    static bool attr_set = false;
    if (!attr_set) {
        cudaFuncSetAttribute(gemm_tc, cudaFuncAttributeMaxDynamicSharedMemorySize, G_TOT);
        attr_set = true;
    }

    // 1) qkv = x @ W_qkv + b_qkv       (tensor, 3xTF32)
    gemm_tc<<<dim3(W3 / 128, MROWS / 128), 256, G_TOT>>>(x, Wqkv, bqkv, qkv, W3, WID);
    // 2) k_mean
    kmean_kernel<<<BATCH * HEADS, 256>>>();
    // 3) pos = (q . k_mean)/8
    pos_kernel<<<BATCH * T_SEQ, 256>>>();
    // 4) adaptive weight
    aw_kernel<<<BATCH, 256>>>();
    // 5) attention (SIMT, proven; applies aw)
    flash_attn<<<dim3(T_SEQ / 64, BATCH * HEADS), 256>>>();
    // 6) out = attn @ W_proj + b_proj  (tensor, 3xTF32)
    gemm_tc<<<dim3(WID / 128, MROWS / 128), 256, G_TOT>>>(attn, Wproj, bproj, out, WID, WID);
}